// round 15
// baseline (speedup 1.0000x reference)
#include <cuda_runtime.h>
#include <cuda_fp16.h>
#include <cstdint>
#include <math.h>

// ---------------- problem constants ----------------
#define T_DIM 512
#define B_DIM 64
#define E_DIM 300
#define H_DIM 800
#define H2    (H_DIM / 2)        // 400 half2 pairs
#define L_DIM 3
#define M_DIM (T_DIM * B_DIM)   // 32768
#define N_OUT 2400              // 3*H
#define N_PADROWS 2432          // N padded to mult of 128
#define KPAD0 320               // 300 -> mult of 64
#define KPAD  832               // 800 -> mult of 64

// fused scan: 16 j2-pairs x 16 t-chunks of 32 (round-13 proven config)
#define SJ 16
#define SCH 16
#define STC (T_DIM / SCH)       // 32

// GEMM tiling
#define BM 128
#define BN 128
#define BK 64
#define STAGES 3
#define STAGE_BYTES 32768       // A 16K | B 16K
#define A_OFF  0
#define B_OFF  16384

// ---------------- static scratch ----------------
__device__ __half g_buf[(size_t)M_DIM * N_OUT];           // post-activation z|f|o (fp16)
__device__ __half A0_buf[(size_t)M_DIM * KPAD0];          // layer0 A operand
__device__ __half A12_buf[(size_t)M_DIM * KPAD];          // layers 1/2 A operand (h); padding stays 0
__device__ __half W0_buf[(size_t)N_PADROWS * KPAD0];
__device__ __half W1_buf[(size_t)N_PADROWS * KPAD];
__device__ __half W2_buf[(size_t)N_PADROWS * KPAD];

// ---------------- helpers ----------------
__device__ __forceinline__ uint32_t smem_u32(const void* p) {
    uint32_t a;
    asm("{ .reg .u64 t; cvta.to.shared.u64 t, %1; cvt.u32.u64 %0, t; }" : "=r"(a) : "l"(p));
    return a;
}
__device__ __forceinline__ void cp16(uint32_t dst, const void* src) {
    asm volatile("cp.async.cg.shared.global [%0], [%1], 16;" :: "r"(dst), "l"(src) : "memory");
}
__device__ __forceinline__ void cp_commit() {
    asm volatile("cp.async.commit_group;" ::: "memory");
}
template <int N> __device__ __forceinline__ void cp_wait() {
    asm volatile("cp.async.wait_group %0;" :: "n"(N) : "memory");
}
__device__ __forceinline__ void ldsm4(uint32_t& r0, uint32_t& r1, uint32_t& r2, uint32_t& r3,
                                      uint32_t addr) {
    asm volatile("ldmatrix.sync.aligned.m8n8.x4.shared.b16 {%0,%1,%2,%3}, [%4];"
                 : "=r"(r0), "=r"(r1), "=r"(r2), "=r"(r3) : "r"(addr));
}
__device__ __forceinline__ void mma_f16(float* c, const uint32_t* a, const uint32_t* b) {
    asm volatile(
        "mma.sync.aligned.m16n8k16.row.col.f32.f16.f16.f32 "
        "{%0,%1,%2,%3}, {%4,%5,%6,%7}, {%8,%9}, {%0,%1,%2,%3};"
        : "+f"(c[0]), "+f"(c[1]), "+f"(c[2]), "+f"(c[3])
        : "r"(a[0]), "r"(a[1]), "r"(a[2]), "r"(a[3]), "r"(b[0]), "r"(b[1]));
}

// f16x2 fast activations (1 MUFU per 2 elements)
__device__ __forceinline__ uint32_t tanh_h2(uint32_t x) {
    uint32_t r;
    asm("tanh.approx.f16x2 %0, %1;" : "=r"(r) : "r"(x));
    return r;
}
__device__ __forceinline__ uint32_t pack_h2(float a, float b) {
    __half2 h = __floats2half2_rn(a, b);
    return *reinterpret_cast<uint32_t*>(&h);
}
// sigmoid(x) = 0.5*tanh(0.5x) + 0.5 (exact identity)
__device__ __forceinline__ uint32_t sigmoid_h2(uint32_t x) {
    const __half2 half_c = __floats2half2_rn(0.5f, 0.5f);
    __half2 xh = *reinterpret_cast<__half2*>(&x);
    __half2 t = __hmul2(xh, half_c);
    uint32_t tu = tanh_h2(*reinterpret_cast<uint32_t*>(&t));
    __half2 th = *reinterpret_cast<__half2*>(&tu);
    __half2 r = __hfma2(th, half_c, half_c);
    return *reinterpret_cast<uint32_t*>(&r);
}

// ---------------- setup: weight transposes (z=0..2) + sent convert (z=3) ----------------
__global__ void setup_kernel(const float* __restrict__ W0, const float* __restrict__ W1,
                             const float* __restrict__ W2, const float* __restrict__ sent,
                             __half* __restrict__ T0, __half* __restrict__ T1,
                             __half* __restrict__ T2) {
    int z = blockIdx.z;
    if (z == 3) {
        // sent fp32 -> fp16 (padded K): flat index over M*(KPAD0/4) float4 chunks
        int i = (blockIdx.y * gridDim.x + blockIdx.x) * 256 + threadIdx.y * 32 + threadIdx.x;
        if (i >= M_DIM * (KPAD0 / 4)) return;
        int row = i / (KPAD0 / 4);
        int j4 = (i % (KPAD0 / 4)) * 4;
        uint2 outv;
        if (j4 < E_DIM) {
            float4 v = *reinterpret_cast<const float4*>(sent + (size_t)row * E_DIM + j4);
            __half2 h0 = __floats2half2_rn(v.x, v.y);
            __half2 h1 = __floats2half2_rn(v.z, v.w);
            outv.x = *reinterpret_cast<uint32_t*>(&h0);
            outv.y = *reinterpret_cast<uint32_t*>(&h1);
        } else {
            outv.x = 0u; outv.y = 0u;
        }
        *reinterpret_cast<uint2*>(&A0_buf[(size_t)row * KPAD0 + j4]) = outv;
        return;
    }
    __shared__ float tile[32][33];
    const float* W = (z == 0) ? W0 : (z == 1) ? W1 : W2;
    __half* Tw = (z == 0) ? T0 : (z == 1) ? T1 : T2;
    int K = (z == 0) ? E_DIM : H_DIM;
    int Kp = (z == 0) ? KPAD0 : KPAD;
    int kb = blockIdx.y * 32, nb = blockIdx.x * 32;
    if (kb >= Kp) return;
    for (int r = threadIdx.y; r < 32; r += 8) {
        int k = kb + r, n = nb + threadIdx.x;
        tile[r][threadIdx.x] = (k < K && n < N_OUT) ? W[(size_t)k * N_OUT + n] : 0.f;
    }
    __syncthreads();
    for (int r = threadIdx.y; r < 32; r += 8) {
        int n = nb + r, k = kb + threadIdx.x;
        Tw[(size_t)n * Kp + k] = __float2half(tile[threadIdx.x][r]);
    }
}

// ---------------- fp16 HMMA GEMM (128x128 tile, BK=64), hoisted addressing ----------
__global__ __launch_bounds__(256, 2)
void qrnn_gemm_kernel(const __half* __restrict__ A, const __half* __restrict__ B,
                      int ldk, int nc,
                      const float* __restrict__ bias, __half* __restrict__ C) {
    extern __shared__ char smem[];
    const uint32_t sbase = smem_u32(smem);

    const int tid = threadIdx.x;
    const int lane = tid & 31;
    const int wid = tid >> 5;
    const int wm = wid >> 2;
    const int wn = wid & 3;
    const int am0 = blockIdx.y * BM;
    const int bn0 = blockIdx.x * BN;

    uint32_t ld_soff[4];
    uint32_t ld_goffA[4];
    uint32_t ld_goffB[4];
#pragma unroll
    for (int i = 0; i < 4; i++) {
        int id = tid + i * 256;
        int row = id >> 3, c = id & 7;
        int sc = c ^ (row & 7);
        ld_soff[i] = row * 128 + sc * 16;
        ld_goffA[i] = (uint32_t)((am0 + row) * ldk + c * 8);
        ld_goffB[i] = (uint32_t)((bn0 + row) * ldk + c * 8);
    }

    auto load_stage = [&](int kc, int st) {
        const uint32_t kof = (uint32_t)kc * BK;
        uint32_t sb = sbase + st * STAGE_BYTES;
#pragma unroll
        for (int i = 0; i < 4; i++) {
            cp16(sb + A_OFF + ld_soff[i], A + ld_goffA[i] + kof);
            cp16(sb + B_OFF + ld_soff[i], B + ld_goffB[i] + kof);
        }
    };

    const int lr = lane & 15;
    const int lc = lane >> 4;
    uint32_t swz[4];
#pragma unroll
    for (int kk = 0; kk < 4; kk++)
        swz[kk] = (uint32_t)(((kk * 2 + lc) ^ (lr & 7)) * 16);
    const uint32_t rowbaseA = (uint32_t)((wm * 64 + lr) * 128);
    const uint32_t rowbaseB = (uint32_t)((wn * 32 + lr) * 128);

    float acc[4][4][4];
#pragma unroll
    for (int i = 0; i < 4; i++)
#pragma unroll
        for (int j = 0; j < 4; j++)
#pragma unroll
            for (int q = 0; q < 4; q++) acc[i][j][q] = 0.f;

    load_stage(0, 0); cp_commit();
    if (nc > 1) { load_stage(1, 1); cp_commit(); }

    int st_cur = 0, st_pre = 2;
    for (int kc = 0; kc < nc; kc++) {
        if (kc + 1 < nc) cp_wait<1>(); else cp_wait<0>();
        __syncthreads();
        if (kc + 2 < nc) {
            load_stage(kc + 2, st_pre); cp_commit();
        }

        const uint32_t sbA = sbase + st_cur * STAGE_BYTES + A_OFF + rowbaseA;
        const uint32_t sbB = sbase + st_cur * STAGE_BYTES + B_OFF + rowbaseB;
        if (++st_cur == STAGES) st_cur = 0;
        if (++st_pre == STAGES) st_pre = 0;

#pragma unroll
        for (int kp = 0; kp < 2; kp++) {
            uint32_t breg[2][4][2];
#pragma unroll
            for (int kk2 = 0; kk2 < 2; kk2++) {
                const uint32_t sw = swz[kp * 2 + kk2];
#pragma unroll
                for (int p = 0; p < 2; p++) {
                    uint32_t r0, r1, r2, r3;
                    ldsm4(r0, r1, r2, r3, sbB + p * 2048 + sw);
                    breg[kk2][2 * p][0] = r0; breg[kk2][2 * p + 1][0] = r1;
                    breg[kk2][2 * p][1] = r2; breg[kk2][2 * p + 1][1] = r3;
                }
            }
#pragma unroll
            for (int kk2 = 0; kk2 < 2; kk2++) {
                const uint32_t sw = swz[kp * 2 + kk2];
#pragma unroll
                for (int mt = 0; mt < 4; mt++) {
                    uint32_t a[4];
                    ldsm4(a[0], a[1], a[2], a[3], sbA + mt * 2048 + sw);
#pragma unroll
                    for (int ng = 0; ng < 4; ng++)
                        mma_f16(acc[mt][ng], a, breg[kk2][ng]);
                }
            }
        }
    }

    // ---- epilogue: bias + f16x2 activation, half2 stores ----
    const int tg = lane >> 2;
    const int tq = lane & 3;
#pragma unroll
    for (int ng = 0; ng < 4; ng++) {
        int colb = bn0 + wn * 32 + ng * 8;
        if (colb >= N_OUT) continue;
        int col = colb + tq * 2;
        float2 bv = *reinterpret_cast<const float2*>(&bias[col]);
        bool is_t = colb < H_DIM;
#pragma unroll
        for (int mt = 0; mt < 4; mt++) {
            int r0 = am0 + wm * 64 + mt * 16 + tg;
            uint32_t p0 = pack_h2(acc[mt][ng][0] + bv.x, acc[mt][ng][1] + bv.y);
            uint32_t p1 = pack_h2(acc[mt][ng][2] + bv.x, acc[mt][ng][3] + bv.y);
            uint32_t v0 = is_t ? tanh_h2(p0) : sigmoid_h2(p0);
            uint32_t v1 = is_t ? tanh_h2(p1) : sigmoid_h2(p1);
            *reinterpret_cast<uint32_t*>(&C[(size_t)r0 * N_OUT + col]) = v0;
            *reinterpret_cast<uint32_t*>(&C[(size_t)(r0 + 8) * N_OUT + col]) = v1;
        }
    }
}

// ---------------- fused fo-pool scan (round-13 config): block-local two-pass ----------
__global__ __launch_bounds__(256)
void qrnn_scan_fused_kernel(const __half* __restrict__ g, __half* __restrict__ H,
                            float* __restrict__ out, int layer, int write_h) {
    __shared__ float2 Pv[SCH][SJ];
    __shared__ float2 Cv[SCH][SJ];

    const int jl = threadIdx.x & 15;
    const int ch = threadIdx.x >> 4;
    const int j2 = blockIdx.x * SJ + jl;
    const int b = blockIdx.y;

    const __half* gp = g + (size_t)b * N_OUT + 2 * j2;
    const int t0b = ch * STC;

    float2 c = make_float2(0.f, 0.f);
    float2 P = make_float2(1.f, 1.f);
    for (int t0 = t0b; t0 < t0b + STC; t0 += 4) {
        float2 zt[4], fs[4];
#pragma unroll
        for (int u = 0; u < 4; u++) {
            size_t base = (size_t)(t0 + u) * B_DIM * N_OUT;
            zt[u] = __half22float2(*reinterpret_cast<const __half2*>(gp + base));
            fs[u] = __half22float2(*reinterpret_cast<const __half2*>(gp + base + H_DIM));
        }
#pragma unroll
        for (int u = 0; u < 4; u++) {
            c.x = fmaf(fs[u].x, zt[u].x - c.x, c.x);
            c.y = fmaf(fs[u].y, zt[u].y - c.y, c.y);
            P.x *= (1.f - fs[u].x);
            P.y *= (1.f - fs[u].y);
        }
    }
    Pv[ch][jl] = P;
    Cv[ch][jl] = c;
    __syncthreads();

    c = make_float2(0.f, 0.f);
    for (int i = 0; i < ch; i++) {
        float2 Ci = Cv[i][jl];
        float2 Pi = Pv[i][jl];
        c.x = Ci.x + Pi.x * c.x;
        c.y = Ci.y + Pi.y * c.y;
    }

    for (int t0 = t0b; t0 < t0b + STC; t0 += 4) {
        float2 zt[4], fs[4], os[4];
#pragma unroll
        for (int u = 0; u < 4; u++) {
            size_t base = (size_t)(t0 + u) * B_DIM * N_OUT;
            zt[u] = __half22float2(*reinterpret_cast<const __half2*>(gp + base));
            fs[u] = __half22float2(*reinterpret_cast<const __half2*>(gp + base + H_DIM));
            os[u] = __half22float2(*reinterpret_cast<const __half2*>(gp + base + 2 * H_DIM));
        }
#pragma unroll
        for (int u = 0; u < 4; u++) {
            c.x = fmaf(fs[u].x, zt[u].x - c.x, c.x);
            c.y = fmaf(fs[u].y, zt[u].y - c.y, c.y);
            if (write_h) {
                __half2 hv = __floats2half2_rn(os[u].x * c.x, os[u].y * c.y);
                *reinterpret_cast<__half2*>(
                    &H[(size_t)((t0 + u) * B_DIM + b) * KPAD + 2 * j2]) = hv;
            }
        }
    }
    if (ch == SCH - 1) {
        *reinterpret_cast<float2*>(
            &out[(size_t)b * (L_DIM * H_DIM) + (size_t)layer * H_DIM + 2 * j2]) = c;
    }
}

// ---------------- launch ----------------
extern "C" void kernel_launch(void* const* d_in, const int* in_sizes, int n_in,
                              void* d_out, int out_size) {
    const float* sent = (const float*)d_in[0];
    const float* W0 = (const float*)d_in[2];
    const float* b0 = (const float*)d_in[3];
    const float* W1 = (const float*)d_in[4];
    const float* b1 = (const float*)d_in[5];
    const float* W2 = (const float*)d_in[6];
    const float* b2 = (const float*)d_in[7];
    float* out = (float*)d_out;

    __half* g;  cudaGetSymbolAddress((void**)&g, g_buf);
    __half *a0, *a12, *w0, *w1, *w2;
    cudaGetSymbolAddress((void**)&a0, A0_buf);
    cudaGetSymbolAddress((void**)&a12, A12_buf);
    cudaGetSymbolAddress((void**)&w0, W0_buf);
    cudaGetSymbolAddress((void**)&w1, W1_buf);
    cudaGetSymbolAddress((void**)&w2, W2_buf);

    cudaFuncSetAttribute(qrnn_gemm_kernel, cudaFuncAttributeMaxDynamicSharedMemorySize,
                         STAGES * STAGE_BYTES);

    {
        // z=0..2: weight transposes; z=3: sent convert.
        // grid x*y blocks per z-slice: 76 x 26 = 1976 >= needed for both roles
        // (sent needs ceil(32768*80/256)=10240... use y to extend: 76*135 >= 10240)
        dim3 wblk(32, 8);
        unsigned gx = N_PADROWS / 32;                 // 76
        unsigned need_sent = (M_DIM * (KPAD0 / 4) + 255) / 256;   // 10240
        unsigned gy = (need_sent + gx - 1) / gx;      // 135
        if (gy < KPAD / 32) gy = KPAD / 32;           // >= 26 for weights
        dim3 wgrid(gx, gy, 4);
        setup_kernel<<<wgrid, wblk>>>(W0, W1, W2, sent, w0, w1, w2);
    }

    dim3 ggrid(N_PADROWS / BN, M_DIM / BM);   // (19, 256)
    size_t smem = STAGES * STAGE_BYTES;
    dim3 sgrid(H2 / SJ, B_DIM);               // (25, 64)

    qrnn_gemm_kernel<<<ggrid, 256, smem>>>(a0, w0, KPAD0, KPAD0 / BK, b0, g);
    qrnn_scan_fused_kernel<<<sgrid, 256>>>(g, a12, out, 0, 1);

    qrnn_gemm_kernel<<<ggrid, 256, smem>>>(a12, w1, KPAD, KPAD / BK, b1, g);
    qrnn_scan_fused_kernel<<<sgrid, 256>>>(g, a12, out, 1, 1);

    qrnn_gemm_kernel<<<ggrid, 256, smem>>>(a12, w2, KPAD, KPAD / BK, b2, g);
    qrnn_scan_fused_kernel<<<sgrid, 256>>>(g, a12, out, 2, 0);
}

// round 16
// speedup vs baseline: 1.0060x; 1.0060x over previous
#include <cuda_runtime.h>
#include <cuda_fp16.h>
#include <cstdint>
#include <math.h>

// ---------------- problem constants ----------------
#define T_DIM 512
#define B_DIM 64
#define E_DIM 300
#define H_DIM 800
#define H2    (H_DIM / 2)        // 400 half2 pairs
#define L_DIM 3
#define M_DIM (T_DIM * B_DIM)   // 32768
#define N_OUT 2400              // 3*H
#define N_PADROWS 2432          // N padded to mult of 128
#define KPAD0 320               // 300 -> mult of 64
#define KPAD  832               // 800 -> mult of 64

// fused scan: 16 j2-pairs x 16 t-chunks of 32 (round-13 proven config)
#define SJ 16
#define SCH 16
#define STC (T_DIM / SCH)       // 32

// GEMM tiling
#define BM 128
#define BN 128
#define BK 64
#define STAGES 3
#define STAGE_BYTES 32768       // A 16K | B 16K
#define A_OFF  0
#define B_OFF  16384

// ---------------- static scratch ----------------
__device__ __half g_buf[(size_t)M_DIM * N_OUT];           // post-activation z|f|o (fp16)
__device__ __half A0_buf[(size_t)M_DIM * KPAD0];          // layer0 A operand
__device__ __half A12_buf[(size_t)M_DIM * KPAD];          // layers 1/2 A operand (h); padding stays 0
__device__ __half W0_buf[(size_t)N_PADROWS * KPAD0];
__device__ __half W1_buf[(size_t)N_PADROWS * KPAD];
__device__ __half W2_buf[(size_t)N_PADROWS * KPAD];

// ---------------- helpers ----------------
__device__ __forceinline__ uint32_t smem_u32(const void* p) {
    uint32_t a;
    asm("{ .reg .u64 t; cvta.to.shared.u64 t, %1; cvt.u32.u64 %0, t; }" : "=r"(a) : "l"(p));
    return a;
}
__device__ __forceinline__ void cp16(uint32_t dst, const void* src) {
    asm volatile("cp.async.cg.shared.global [%0], [%1], 16;" :: "r"(dst), "l"(src) : "memory");
}
__device__ __forceinline__ void cp_commit() {
    asm volatile("cp.async.commit_group;" ::: "memory");
}
template <int N> __device__ __forceinline__ void cp_wait() {
    asm volatile("cp.async.wait_group %0;" :: "n"(N) : "memory");
}
__device__ __forceinline__ void ldsm4(uint32_t& r0, uint32_t& r1, uint32_t& r2, uint32_t& r3,
                                      uint32_t addr) {
    asm volatile("ldmatrix.sync.aligned.m8n8.x4.shared.b16 {%0,%1,%2,%3}, [%4];"
                 : "=r"(r0), "=r"(r1), "=r"(r2), "=r"(r3) : "r"(addr));
}
__device__ __forceinline__ void mma_f16(float* c, const uint32_t* a, const uint32_t* b) {
    asm volatile(
        "mma.sync.aligned.m16n8k16.row.col.f32.f16.f16.f32 "
        "{%0,%1,%2,%3}, {%4,%5,%6,%7}, {%8,%9}, {%0,%1,%2,%3};"
        : "+f"(c[0]), "+f"(c[1]), "+f"(c[2]), "+f"(c[3])
        : "r"(a[0]), "r"(a[1]), "r"(a[2]), "r"(a[3]), "r"(b[0]), "r"(b[1]));
}

// f16x2 fast activations (1 MUFU per 2 elements)
__device__ __forceinline__ uint32_t tanh_h2(uint32_t x) {
    uint32_t r;
    asm("tanh.approx.f16x2 %0, %1;" : "=r"(r) : "r"(x));
    return r;
}
__device__ __forceinline__ uint32_t pack_h2(float a, float b) {
    __half2 h = __floats2half2_rn(a, b);
    return *reinterpret_cast<uint32_t*>(&h);
}
// sigmoid(x) = 0.5*tanh(0.5x) + 0.5 (exact identity)
__device__ __forceinline__ uint32_t sigmoid_h2(uint32_t x) {
    const __half2 half_c = __floats2half2_rn(0.5f, 0.5f);
    __half2 xh = *reinterpret_cast<__half2*>(&x);
    __half2 t = __hmul2(xh, half_c);
    uint32_t tu = tanh_h2(*reinterpret_cast<uint32_t*>(&t));
    __half2 th = *reinterpret_cast<__half2*>(&tu);
    __half2 r = __hfma2(th, half_c, half_c);
    return *reinterpret_cast<uint32_t*>(&r);
}

// ---------------- weight transpose fp16 (all 3 layers in one launch) ----------------
__global__ void conv_w_all_kernel(const float* __restrict__ W0, const float* __restrict__ W1,
                                  const float* __restrict__ W2,
                                  __half* __restrict__ T0, __half* __restrict__ T1,
                                  __half* __restrict__ T2) {
    __shared__ float tile[32][33];
    int layer = blockIdx.z;
    const float* W = (layer == 0) ? W0 : (layer == 1) ? W1 : W2;
    __half* Tw = (layer == 0) ? T0 : (layer == 1) ? T1 : T2;
    int K = (layer == 0) ? E_DIM : H_DIM;
    int Kp = (layer == 0) ? KPAD0 : KPAD;
    int kb = blockIdx.y * 32, nb = blockIdx.x * 32;
    if (kb >= Kp) return;
    for (int r = threadIdx.y; r < 32; r += 8) {
        int k = kb + r, n = nb + threadIdx.x;
        tile[r][threadIdx.x] = (k < K && n < N_OUT) ? W[(size_t)k * N_OUT + n] : 0.f;
    }
    __syncthreads();
    for (int r = threadIdx.y; r < 32; r += 8) {
        int n = nb + r, k = kb + threadIdx.x;
        Tw[(size_t)n * Kp + k] = __float2half(tile[threadIdx.x][r]);
    }
}

// ---------------- sent fp32 -> fp16 (padded K), vectorized ----------------
__global__ void conv_sent_kernel(const float* __restrict__ x) {
    int i = blockIdx.x * 256 + threadIdx.x;
    if (i >= M_DIM * (KPAD0 / 4)) return;
    int row = i / (KPAD0 / 4);
    int j4 = (i % (KPAD0 / 4)) * 4;
    uint2 outv;
    if (j4 < E_DIM) {
        float4 v = *reinterpret_cast<const float4*>(x + (size_t)row * E_DIM + j4);
        __half2 h0 = __floats2half2_rn(v.x, v.y);
        __half2 h1 = __floats2half2_rn(v.z, v.w);
        outv.x = *reinterpret_cast<uint32_t*>(&h0);
        outv.y = *reinterpret_cast<uint32_t*>(&h1);
    } else {
        outv.x = 0u; outv.y = 0u;
    }
    *reinterpret_cast<uint2*>(&A0_buf[(size_t)row * KPAD0 + j4]) = outv;
}

// ---------------- fp16 HMMA GEMM (128x128, BK=64), pipelined A-ldsm ----------------
__global__ __launch_bounds__(256, 2)
void qrnn_gemm_kernel(const __half* __restrict__ A, const __half* __restrict__ B,
                      int ldk, int nc,
                      const float* __restrict__ bias, __half* __restrict__ C) {
    extern __shared__ char smem[];
    const uint32_t sbase = smem_u32(smem);

    const int tid = threadIdx.x;
    const int lane = tid & 31;
    const int wid = tid >> 5;
    const int wm = wid >> 2;
    const int wn = wid & 3;
    const int am0 = blockIdx.y * BM;
    const int bn0 = blockIdx.x * BN;

    uint32_t ld_soff[4];
    uint32_t ld_goffA[4];
    uint32_t ld_goffB[4];
#pragma unroll
    for (int i = 0; i < 4; i++) {
        int id = tid + i * 256;
        int row = id >> 3, c = id & 7;
        int sc = c ^ (row & 7);
        ld_soff[i] = row * 128 + sc * 16;
        ld_goffA[i] = (uint32_t)((am0 + row) * ldk + c * 8);
        ld_goffB[i] = (uint32_t)((bn0 + row) * ldk + c * 8);
    }

    auto load_stage = [&](int kc, int st) {
        const uint32_t kof = (uint32_t)kc * BK;
        uint32_t sb = sbase + st * STAGE_BYTES;
#pragma unroll
        for (int i = 0; i < 4; i++) {
            cp16(sb + A_OFF + ld_soff[i], A + ld_goffA[i] + kof);
            cp16(sb + B_OFF + ld_soff[i], B + ld_goffB[i] + kof);
        }
    };

    const int lr = lane & 15;
    const int lc = lane >> 4;
    uint32_t swz[4];
#pragma unroll
    for (int kk = 0; kk < 4; kk++)
        swz[kk] = (uint32_t)(((kk * 2 + lc) ^ (lr & 7)) * 16);
    const uint32_t rowbaseA = (uint32_t)((wm * 64 + lr) * 128);
    const uint32_t rowbaseB = (uint32_t)((wn * 32 + lr) * 128);

    float acc[4][4][4];
#pragma unroll
    for (int i = 0; i < 4; i++)
#pragma unroll
        for (int j = 0; j < 4; j++)
#pragma unroll
            for (int q = 0; q < 4; q++) acc[i][j][q] = 0.f;

    load_stage(0, 0); cp_commit();
    if (nc > 1) { load_stage(1, 1); cp_commit(); }

    int st_cur = 0, st_pre = 2;
    for (int kc = 0; kc < nc; kc++) {
        if (kc + 1 < nc) cp_wait<1>(); else cp_wait<0>();
        __syncthreads();
        if (kc + 2 < nc) {
            load_stage(kc + 2, st_pre); cp_commit();
        }

        const uint32_t sbA = sbase + st_cur * STAGE_BYTES + A_OFF + rowbaseA;
        const uint32_t sbB = sbase + st_cur * STAGE_BYTES + B_OFF + rowbaseB;
        if (++st_cur == STAGES) st_cur = 0;
        if (++st_pre == STAGES) st_pre = 0;

#pragma unroll
        for (int kp = 0; kp < 2; kp++) {
            const uint32_t sw0 = swz[kp * 2 + 0];
            const uint32_t sw1 = swz[kp * 2 + 1];

            // B fragments for both kk halves
            uint32_t breg[2][4][2];
#pragma unroll
            for (int kk2 = 0; kk2 < 2; kk2++) {
                const uint32_t sw = (kk2 == 0) ? sw0 : sw1;
#pragma unroll
                for (int p = 0; p < 2; p++) {
                    uint32_t r0, r1, r2, r3;
                    ldsm4(r0, r1, r2, r3, sbB + p * 2048 + sw);
                    breg[kk2][2 * p][0] = r0; breg[kk2][2 * p + 1][0] = r1;
                    breg[kk2][2 * p][1] = r2; breg[kk2][2 * p + 1][1] = r3;
                }
            }

            // A-ldsm / MMA software pipeline (ping-pong aP/aQ).
            // Accumulation order per acc[mt][ng]: kk2=0 then kk2=1 (unchanged).
            uint32_t aP[4], aQ[4];
            ldsm4(aP[0], aP[1], aP[2], aP[3], sbA + 0 * 2048 + sw0);   // (k0,m0)
            ldsm4(aQ[0], aQ[1], aQ[2], aQ[3], sbA + 1 * 2048 + sw0);   // (k0,m1)
#pragma unroll
            for (int ng = 0; ng < 4; ng++) mma_f16(acc[0][ng], aP, breg[0][ng]);
            ldsm4(aP[0], aP[1], aP[2], aP[3], sbA + 2 * 2048 + sw0);   // (k0,m2)
#pragma unroll
            for (int ng = 0; ng < 4; ng++) mma_f16(acc[1][ng], aQ, breg[0][ng]);
            ldsm4(aQ[0], aQ[1], aQ[2], aQ[3], sbA + 3 * 2048 + sw0);   // (k0,m3)
#pragma unroll
            for (int ng = 0; ng < 4; ng++) mma_f16(acc[2][ng], aP, breg[0][ng]);
            ldsm4(aP[0], aP[1], aP[2], aP[3], sbA + 0 * 2048 + sw1);   // (k1,m0)
#pragma unroll
            for (int ng = 0; ng < 4; ng++) mma_f16(acc[3][ng], aQ, breg[0][ng]);
            ldsm4(aQ[0], aQ[1], aQ[2], aQ[3], sbA + 1 * 2048 + sw1);   // (k1,m1)
#pragma unroll
            for (int ng = 0; ng < 4; ng++) mma_f16(acc[0][ng], aP, breg[1][ng]);
            ldsm4(aP[0], aP[1], aP[2], aP[3], sbA + 2 * 2048 + sw1);   // (k1,m2)
#pragma unroll
            for (int ng = 0; ng < 4; ng++) mma_f16(acc[1][ng], aQ, breg[1][ng]);
            ldsm4(aQ[0], aQ[1], aQ[2], aQ[3], sbA + 3 * 2048 + sw1);   // (k1,m3)
#pragma unroll
            for (int ng = 0; ng < 4; ng++) mma_f16(acc[2][ng], aP, breg[1][ng]);
#pragma unroll
            for (int ng = 0; ng < 4; ng++) mma_f16(acc[3][ng], aQ, breg[1][ng]);
        }
    }

    // ---- epilogue: bias + f16x2 activation, half2 stores ----
    const int tg = lane >> 2;
    const int tq = lane & 3;
#pragma unroll
    for (int ng = 0; ng < 4; ng++) {
        int colb = bn0 + wn * 32 + ng * 8;
        if (colb >= N_OUT) continue;
        int col = colb + tq * 2;
        float2 bv = *reinterpret_cast<const float2*>(&bias[col]);
        bool is_t = colb < H_DIM;
#pragma unroll
        for (int mt = 0; mt < 4; mt++) {
            int r0 = am0 + wm * 64 + mt * 16 + tg;
            uint32_t p0 = pack_h2(acc[mt][ng][0] + bv.x, acc[mt][ng][1] + bv.y);
            uint32_t p1 = pack_h2(acc[mt][ng][2] + bv.x, acc[mt][ng][3] + bv.y);
            uint32_t v0 = is_t ? tanh_h2(p0) : sigmoid_h2(p0);
            uint32_t v1 = is_t ? tanh_h2(p1) : sigmoid_h2(p1);
            *reinterpret_cast<uint32_t*>(&C[(size_t)r0 * N_OUT + col]) = v0;
            *reinterpret_cast<uint32_t*>(&C[(size_t)(r0 + 8) * N_OUT + col]) = v1;
        }
    }
}

// ---------------- fused fo-pool scan (round-13 config): block-local two-pass ----------
__global__ __launch_bounds__(256)
void qrnn_scan_fused_kernel(const __half* __restrict__ g, __half* __restrict__ H,
                            float* __restrict__ out, int layer, int write_h) {
    __shared__ float2 Pv[SCH][SJ];
    __shared__ float2 Cv[SCH][SJ];

    const int jl = threadIdx.x & 15;
    const int ch = threadIdx.x >> 4;
    const int j2 = blockIdx.x * SJ + jl;
    const int b = blockIdx.y;

    const __half* gp = g + (size_t)b * N_OUT + 2 * j2;
    const int t0b = ch * STC;

    float2 c = make_float2(0.f, 0.f);
    float2 P = make_float2(1.f, 1.f);
    for (int t0 = t0b; t0 < t0b + STC; t0 += 4) {
        float2 zt[4], fs[4];
#pragma unroll
        for (int u = 0; u < 4; u++) {
            size_t base = (size_t)(t0 + u) * B_DIM * N_OUT;
            zt[u] = __half22float2(*reinterpret_cast<const __half2*>(gp + base));
            fs[u] = __half22float2(*reinterpret_cast<const __half2*>(gp + base + H_DIM));
        }
#pragma unroll
        for (int u = 0; u < 4; u++) {
            c.x = fmaf(fs[u].x, zt[u].x - c.x, c.x);
            c.y = fmaf(fs[u].y, zt[u].y - c.y, c.y);
            P.x *= (1.f - fs[u].x);
            P.y *= (1.f - fs[u].y);
        }
    }
    Pv[ch][jl] = P;
    Cv[ch][jl] = c;
    __syncthreads();

    c = make_float2(0.f, 0.f);
    for (int i = 0; i < ch; i++) {
        float2 Ci = Cv[i][jl];
        float2 Pi = Pv[i][jl];
        c.x = Ci.x + Pi.x * c.x;
        c.y = Ci.y + Pi.y * c.y;
    }

    for (int t0 = t0b; t0 < t0b + STC; t0 += 4) {
        float2 zt[4], fs[4], os[4];
#pragma unroll
        for (int u = 0; u < 4; u++) {
            size_t base = (size_t)(t0 + u) * B_DIM * N_OUT;
            zt[u] = __half22float2(*reinterpret_cast<const __half2*>(gp + base));
            fs[u] = __half22float2(*reinterpret_cast<const __half2*>(gp + base + H_DIM));
            os[u] = __half22float2(*reinterpret_cast<const __half2*>(gp + base + 2 * H_DIM));
        }
#pragma unroll
        for (int u = 0; u < 4; u++) {
            c.x = fmaf(fs[u].x, zt[u].x - c.x, c.x);
            c.y = fmaf(fs[u].y, zt[u].y - c.y, c.y);
            if (write_h) {
                __half2 hv = __floats2half2_rn(os[u].x * c.x, os[u].y * c.y);
                *reinterpret_cast<__half2*>(
                    &H[(size_t)((t0 + u) * B_DIM + b) * KPAD + 2 * j2]) = hv;
            }
        }
    }
    if (ch == SCH - 1) {
        *reinterpret_cast<float2*>(
            &out[(size_t)b * (L_DIM * H_DIM) + (size_t)layer * H_DIM + 2 * j2]) = c;
    }
}

// ---------------- launch ----------------
extern "C" void kernel_launch(void* const* d_in, const int* in_sizes, int n_in,
                              void* d_out, int out_size) {
    const float* sent = (const float*)d_in[0];
    const float* W0 = (const float*)d_in[2];
    const float* b0 = (const float*)d_in[3];
    const float* W1 = (const float*)d_in[4];
    const float* b1 = (const float*)d_in[5];
    const float* W2 = (const float*)d_in[6];
    const float* b2 = (const float*)d_in[7];
    float* out = (float*)d_out;

    __half* g;  cudaGetSymbolAddress((void**)&g, g_buf);
    __half *a0, *a12, *w0, *w1, *w2;
    cudaGetSymbolAddress((void**)&a0, A0_buf);
    cudaGetSymbolAddress((void**)&a12, A12_buf);
    cudaGetSymbolAddress((void**)&w0, W0_buf);
    cudaGetSymbolAddress((void**)&w1, W1_buf);
    cudaGetSymbolAddress((void**)&w2, W2_buf);

    cudaFuncSetAttribute(qrnn_gemm_kernel, cudaFuncAttributeMaxDynamicSharedMemorySize,
                         STAGES * STAGE_BYTES);

    {
        dim3 wblk(32, 8);
        dim3 wgrid(N_PADROWS / 32, KPAD / 32, 3);
        conv_w_all_kernel<<<wgrid, wblk>>>(W0, W1, W2, w0, w1, w2);
    }
    {
        int n = M_DIM * (KPAD0 / 4);
        conv_sent_kernel<<<(n + 255) / 256, 256>>>(sent);
    }

    dim3 ggrid(N_PADROWS / BN, M_DIM / BM);   // (19, 256)
    size_t smem = STAGES * STAGE_BYTES;
    dim3 sgrid(H2 / SJ, B_DIM);               // (25, 64)

    qrnn_gemm_kernel<<<ggrid, 256, smem>>>(a0, w0, KPAD0, KPAD0 / BK, b0, g);
    qrnn_scan_fused_kernel<<<sgrid, 256>>>(g, a12, out, 0, 1);

    qrnn_gemm_kernel<<<ggrid, 256, smem>>>(a12, w1, KPAD, KPAD / BK, b1, g);
    qrnn_scan_fused_kernel<<<sgrid, 256>>>(g, a12, out, 1, 1);

    qrnn_gemm_kernel<<<ggrid, 256, smem>>>(a12, w2, KPAD, KPAD / BK, b2, g);
    qrnn_scan_fused_kernel<<<sgrid, 256>>>(g, a12, out, 2, 0);
}

// round 17
// speedup vs baseline: 1.0294x; 1.0233x over previous
#include <cuda_runtime.h>
#include <cuda_fp16.h>
#include <cstdint>
#include <math.h>

// ---------------- problem constants ----------------
#define T_DIM 512
#define B_DIM 64
#define E_DIM 300
#define H_DIM 800
#define H2    (H_DIM / 2)        // 400 half2 pairs
#define L_DIM 3
#define M_DIM (T_DIM * B_DIM)   // 32768
#define N_OUT 2400              // 3*H
#define N_PADROWS 2432          // N padded to mult of 128
#define KPAD0 320               // 300 -> mult of 64
#define KPAD  832               // 800 -> mult of 64

// fused scan: 16 j2-pairs x 16 t-chunks of 32 (round-13 proven config)
#define SJ 16
#define SCH 16
#define STC (T_DIM / SCH)       // 32

// GEMM tiling
#define BM 128
#define BN 128
#define BK 64
#define STAGES 3
#define STAGE_BYTES 32768       // A 16K | B 16K
#define A_OFF  0
#define B_OFF  16384

// ---------------- static scratch ----------------
__device__ __half g_buf[(size_t)M_DIM * N_OUT];           // post-activation z|f|o (fp16)
__device__ __half A0_buf[(size_t)M_DIM * KPAD0];          // layer0 A operand
__device__ __half A12_buf[(size_t)M_DIM * KPAD];          // layers 1/2 A operand (h); padding stays 0
__device__ __half W0_buf[(size_t)N_PADROWS * KPAD0];
__device__ __half W1_buf[(size_t)N_PADROWS * KPAD];
__device__ __half W2_buf[(size_t)N_PADROWS * KPAD];

// ---------------- helpers ----------------
__device__ __forceinline__ uint32_t smem_u32(const void* p) {
    uint32_t a;
    asm("{ .reg .u64 t; cvta.to.shared.u64 t, %1; cvt.u32.u64 %0, t; }" : "=r"(a) : "l"(p));
    return a;
}
__device__ __forceinline__ void cp16(uint32_t dst, const void* src) {
    asm volatile("cp.async.cg.shared.global [%0], [%1], 16;" :: "r"(dst), "l"(src) : "memory");
}
__device__ __forceinline__ void cp_commit() {
    asm volatile("cp.async.commit_group;" ::: "memory");
}
template <int N> __device__ __forceinline__ void cp_wait() {
    asm volatile("cp.async.wait_group %0;" :: "n"(N) : "memory");
}
__device__ __forceinline__ void ldsm4(uint32_t& r0, uint32_t& r1, uint32_t& r2, uint32_t& r3,
                                      uint32_t addr) {
    asm volatile("ldmatrix.sync.aligned.m8n8.x4.shared.b16 {%0,%1,%2,%3}, [%4];"
                 : "=r"(r0), "=r"(r1), "=r"(r2), "=r"(r3) : "r"(addr));
}
__device__ __forceinline__ void mma_f16(float* c, const uint32_t* a, const uint32_t* b) {
    asm volatile(
        "mma.sync.aligned.m16n8k16.row.col.f32.f16.f16.f32 "
        "{%0,%1,%2,%3}, {%4,%5,%6,%7}, {%8,%9}, {%0,%1,%2,%3};"
        : "+f"(c[0]), "+f"(c[1]), "+f"(c[2]), "+f"(c[3])
        : "r"(a[0]), "r"(a[1]), "r"(a[2]), "r"(a[3]), "r"(b[0]), "r"(b[1]));
}

// f16x2 fast activations (1 MUFU per 2 elements)
__device__ __forceinline__ uint32_t tanh_h2(uint32_t x) {
    uint32_t r;
    asm("tanh.approx.f16x2 %0, %1;" : "=r"(r) : "r"(x));
    return r;
}
__device__ __forceinline__ uint32_t pack_h2(float a, float b) {
    __half2 h = __floats2half2_rn(a, b);
    return *reinterpret_cast<uint32_t*>(&h);
}
// sigmoid(x) = 0.5*tanh(0.5x) + 0.5 (exact identity)
__device__ __forceinline__ uint32_t sigmoid_h2(uint32_t x) {
    const __half2 half_c = __floats2half2_rn(0.5f, 0.5f);
    __half2 xh = *reinterpret_cast<__half2*>(&x);
    __half2 t = __hmul2(xh, half_c);
    uint32_t tu = tanh_h2(*reinterpret_cast<uint32_t*>(&t));
    __half2 th = *reinterpret_cast<__half2*>(&tu);
    __half2 r = __hfma2(th, half_c, half_c);
    return *reinterpret_cast<uint32_t*>(&r);
}

// ---------------- weight transpose fp16 (all 3 layers in one launch) ----------------
__global__ void conv_w_all_kernel(const float* __restrict__ W0, const float* __restrict__ W1,
                                  const float* __restrict__ W2,
                                  __half* __restrict__ T0, __half* __restrict__ T1,
                                  __half* __restrict__ T2) {
    __shared__ float tile[32][33];
    int layer = blockIdx.z;
    const float* W = (layer == 0) ? W0 : (layer == 1) ? W1 : W2;
    __half* Tw = (layer == 0) ? T0 : (layer == 1) ? T1 : T2;
    int K = (layer == 0) ? E_DIM : H_DIM;
    int Kp = (layer == 0) ? KPAD0 : KPAD;
    int kb = blockIdx.y * 32, nb = blockIdx.x * 32;
    if (kb >= Kp) return;
    for (int r = threadIdx.y; r < 32; r += 8) {
        int k = kb + r, n = nb + threadIdx.x;
        tile[r][threadIdx.x] = (k < K && n < N_OUT) ? W[(size_t)k * N_OUT + n] : 0.f;
    }
    __syncthreads();
    for (int r = threadIdx.y; r < 32; r += 8) {
        int n = nb + r, k = kb + threadIdx.x;
        Tw[(size_t)n * Kp + k] = __float2half(tile[threadIdx.x][r]);
    }
}

// ---------------- sent fp32 -> fp16 (padded K), vectorized ----------------
__global__ void conv_sent_kernel(const float* __restrict__ x) {
    int i = blockIdx.x * 256 + threadIdx.x;
    if (i >= M_DIM * (KPAD0 / 4)) return;
    int row = i / (KPAD0 / 4);
    int j4 = (i % (KPAD0 / 4)) * 4;
    uint2 outv;
    if (j4 < E_DIM) {
        float4 v = *reinterpret_cast<const float4*>(x + (size_t)row * E_DIM + j4);
        __half2 h0 = __floats2half2_rn(v.x, v.y);
        __half2 h1 = __floats2half2_rn(v.z, v.w);
        outv.x = *reinterpret_cast<uint32_t*>(&h0);
        outv.y = *reinterpret_cast<uint32_t*>(&h1);
    } else {
        outv.x = 0u; outv.y = 0u;
    }
    *reinterpret_cast<uint2*>(&A0_buf[(size_t)row * KPAD0 + j4]) = outv;
}

// chunk compute body: NKK = number of k16 groups (4 normal; 2 or 3 in K-tail).
// Skipped groups multiply zero-padded A by zero-padded W: acc + 0*0 keeps acc
// bitwise-identical, so trimming cannot change results.
#define CHUNK_BODY(NKK)                                                         \
    _Pragma("unroll")                                                           \
    for (int kp = 0; kp < 2; kp++) {                                            \
        if (kp * 2 >= (NKK)) break;                                             \
        uint32_t breg[2][4][2];                                                 \
        _Pragma("unroll")                                                       \
        for (int kk2 = 0; kk2 < 2; kk2++) {                                     \
            if (kp * 2 + kk2 >= (NKK)) break;                                   \
            const uint32_t sw = swz[kp * 2 + kk2];                              \
            _Pragma("unroll")                                                   \
            for (int p = 0; p < 2; p++) {                                       \
                uint32_t r0, r1, r2, r3;                                        \
                ldsm4(r0, r1, r2, r3, sbB + p * 2048 + sw);                     \
                breg[kk2][2 * p][0] = r0; breg[kk2][2 * p + 1][0] = r1;         \
                breg[kk2][2 * p][1] = r2; breg[kk2][2 * p + 1][1] = r3;         \
            }                                                                   \
        }                                                                       \
        _Pragma("unroll")                                                       \
        for (int kk2 = 0; kk2 < 2; kk2++) {                                     \
            if (kp * 2 + kk2 >= (NKK)) break;                                   \
            const uint32_t sw = swz[kp * 2 + kk2];                              \
            _Pragma("unroll")                                                   \
            for (int mt = 0; mt < 4; mt++) {                                    \
                uint32_t a[4];                                                  \
                ldsm4(a[0], a[1], a[2], a[3], sbA + mt * 2048 + sw);            \
                _Pragma("unroll")                                               \
                for (int ng = 0; ng < 4; ng++)                                  \
                    mma_f16(acc[mt][ng], a, breg[kk2][ng]);                     \
            }                                                                   \
        }                                                                       \
    }

// ---------------- fp16 HMMA GEMM (128x128 tile, BK=64), K-tail trimmed ----------
__global__ __launch_bounds__(256, 2)
void qrnn_gemm_kernel(const __half* __restrict__ A, const __half* __restrict__ B,
                      int ldk, int nc, int kk_tail,
                      const float* __restrict__ bias, __half* __restrict__ C) {
    extern __shared__ char smem[];
    const uint32_t sbase = smem_u32(smem);

    const int tid = threadIdx.x;
    const int lane = tid & 31;
    const int wid = tid >> 5;
    const int wm = wid >> 2;
    const int wn = wid & 3;
    const int am0 = blockIdx.y * BM;
    const int bn0 = blockIdx.x * BN;

    uint32_t ld_soff[4];
    uint32_t ld_goffA[4];
    uint32_t ld_goffB[4];
#pragma unroll
    for (int i = 0; i < 4; i++) {
        int id = tid + i * 256;
        int row = id >> 3, c = id & 7;
        int sc = c ^ (row & 7);
        ld_soff[i] = row * 128 + sc * 16;
        ld_goffA[i] = (uint32_t)((am0 + row) * ldk + c * 8);
        ld_goffB[i] = (uint32_t)((bn0 + row) * ldk + c * 8);
    }

    auto load_stage = [&](int kc, int st) {
        const uint32_t kof = (uint32_t)kc * BK;
        uint32_t sb = sbase + st * STAGE_BYTES;
#pragma unroll
        for (int i = 0; i < 4; i++) {
            cp16(sb + A_OFF + ld_soff[i], A + ld_goffA[i] + kof);
            cp16(sb + B_OFF + ld_soff[i], B + ld_goffB[i] + kof);
        }
    };

    const int lr = lane & 15;
    const int lc = lane >> 4;
    uint32_t swz[4];
#pragma unroll
    for (int kk = 0; kk < 4; kk++)
        swz[kk] = (uint32_t)(((kk * 2 + lc) ^ (lr & 7)) * 16);
    const uint32_t rowbaseA = (uint32_t)((wm * 64 + lr) * 128);
    const uint32_t rowbaseB = (uint32_t)((wn * 32 + lr) * 128);

    float acc[4][4][4];
#pragma unroll
    for (int i = 0; i < 4; i++)
#pragma unroll
        for (int j = 0; j < 4; j++)
#pragma unroll
            for (int q = 0; q < 4; q++) acc[i][j][q] = 0.f;

    load_stage(0, 0); cp_commit();
    if (nc > 1) { load_stage(1, 1); cp_commit(); }

    int st_cur = 0, st_pre = 2;
    for (int kc = 0; kc < nc; kc++) {
        if (kc + 1 < nc) cp_wait<1>(); else cp_wait<0>();
        __syncthreads();
        if (kc + 2 < nc) {
            load_stage(kc + 2, st_pre); cp_commit();
        }

        const uint32_t sbA = sbase + st_cur * STAGE_BYTES + A_OFF + rowbaseA;
        const uint32_t sbB = sbase + st_cur * STAGE_BYTES + B_OFF + rowbaseB;
        if (++st_cur == STAGES) st_cur = 0;
        if (++st_pre == STAGES) st_pre = 0;

        if (kc + 1 < nc) {
            CHUNK_BODY(4)
        } else if (kk_tail == 2) {
            CHUNK_BODY(2)
        } else if (kk_tail == 3) {
            CHUNK_BODY(3)
        } else {
            CHUNK_BODY(4)
        }
    }

    // ---- epilogue: bias + f16x2 activation, half2 stores ----
    const int tg = lane >> 2;
    const int tq = lane & 3;
#pragma unroll
    for (int ng = 0; ng < 4; ng++) {
        int colb = bn0 + wn * 32 + ng * 8;
        if (colb >= N_OUT) continue;
        int col = colb + tq * 2;
        float2 bv = *reinterpret_cast<const float2*>(&bias[col]);
        bool is_t = colb < H_DIM;
#pragma unroll
        for (int mt = 0; mt < 4; mt++) {
            int r0 = am0 + wm * 64 + mt * 16 + tg;
            uint32_t p0 = pack_h2(acc[mt][ng][0] + bv.x, acc[mt][ng][1] + bv.y);
            uint32_t p1 = pack_h2(acc[mt][ng][2] + bv.x, acc[mt][ng][3] + bv.y);
            uint32_t v0 = is_t ? tanh_h2(p0) : sigmoid_h2(p0);
            uint32_t v1 = is_t ? tanh_h2(p1) : sigmoid_h2(p1);
            *reinterpret_cast<uint32_t*>(&C[(size_t)r0 * N_OUT + col]) = v0;
            *reinterpret_cast<uint32_t*>(&C[(size_t)(r0 + 8) * N_OUT + col]) = v1;
        }
    }
}

// ---------------- fused fo-pool scan (round-13 config): block-local two-pass ----------
__global__ __launch_bounds__(256)
void qrnn_scan_fused_kernel(const __half* __restrict__ g, __half* __restrict__ H,
                            float* __restrict__ out, int layer, int write_h) {
    __shared__ float2 Pv[SCH][SJ];
    __shared__ float2 Cv[SCH][SJ];

    const int jl = threadIdx.x & 15;
    const int ch = threadIdx.x >> 4;
    const int j2 = blockIdx.x * SJ + jl;
    const int b = blockIdx.y;

    const __half* gp = g + (size_t)b * N_OUT + 2 * j2;
    const int t0b = ch * STC;

    float2 c = make_float2(0.f, 0.f);
    float2 P = make_float2(1.f, 1.f);
    for (int t0 = t0b; t0 < t0b + STC; t0 += 4) {
        float2 zt[4], fs[4];
#pragma unroll
        for (int u = 0; u < 4; u++) {
            size_t base = (size_t)(t0 + u) * B_DIM * N_OUT;
            zt[u] = __half22float2(*reinterpret_cast<const __half2*>(gp + base));
            fs[u] = __half22float2(*reinterpret_cast<const __half2*>(gp + base + H_DIM));
        }
#pragma unroll
        for (int u = 0; u < 4; u++) {
            c.x = fmaf(fs[u].x, zt[u].x - c.x, c.x);
            c.y = fmaf(fs[u].y, zt[u].y - c.y, c.y);
            P.x *= (1.f - fs[u].x);
            P.y *= (1.f - fs[u].y);
        }
    }
    Pv[ch][jl] = P;
    Cv[ch][jl] = c;
    __syncthreads();

    c = make_float2(0.f, 0.f);
    for (int i = 0; i < ch; i++) {
        float2 Ci = Cv[i][jl];
        float2 Pi = Pv[i][jl];
        c.x = Ci.x + Pi.x * c.x;
        c.y = Ci.y + Pi.y * c.y;
    }

    for (int t0 = t0b; t0 < t0b + STC; t0 += 4) {
        float2 zt[4], fs[4], os[4];
#pragma unroll
        for (int u = 0; u < 4; u++) {
            size_t base = (size_t)(t0 + u) * B_DIM * N_OUT;
            zt[u] = __half22float2(*reinterpret_cast<const __half2*>(gp + base));
            fs[u] = __half22float2(*reinterpret_cast<const __half2*>(gp + base + H_DIM));
            os[u] = __half22float2(*reinterpret_cast<const __half2*>(gp + base + 2 * H_DIM));
        }
#pragma unroll
        for (int u = 0; u < 4; u++) {
            c.x = fmaf(fs[u].x, zt[u].x - c.x, c.x);
            c.y = fmaf(fs[u].y, zt[u].y - c.y, c.y);
            if (write_h) {
                __half2 hv = __floats2half2_rn(os[u].x * c.x, os[u].y * c.y);
                *reinterpret_cast<__half2*>(
                    &H[(size_t)((t0 + u) * B_DIM + b) * KPAD + 2 * j2]) = hv;
            }
        }
    }
    if (ch == SCH - 1) {
        *reinterpret_cast<float2*>(
            &out[(size_t)b * (L_DIM * H_DIM) + (size_t)layer * H_DIM + 2 * j2]) = c;
    }
}

// ---------------- launch ----------------
extern "C" void kernel_launch(void* const* d_in, const int* in_sizes, int n_in,
                              void* d_out, int out_size) {
    const float* sent = (const float*)d_in[0];
    const float* W0 = (const float*)d_in[2];
    const float* b0 = (const float*)d_in[3];
    const float* W1 = (const float*)d_in[4];
    const float* b1 = (const float*)d_in[5];
    const float* W2 = (const float*)d_in[6];
    const float* b2 = (const float*)d_in[7];
    float* out = (float*)d_out;

    __half* g;  cudaGetSymbolAddress((void**)&g, g_buf);
    __half *a0, *a12, *w0, *w1, *w2;
    cudaGetSymbolAddress((void**)&a0, A0_buf);
    cudaGetSymbolAddress((void**)&a12, A12_buf);
    cudaGetSymbolAddress((void**)&w0, W0_buf);
    cudaGetSymbolAddress((void**)&w1, W1_buf);
    cudaGetSymbolAddress((void**)&w2, W2_buf);

    cudaFuncSetAttribute(qrnn_gemm_kernel, cudaFuncAttributeMaxDynamicSharedMemorySize,
                         STAGES * STAGE_BYTES);

    {
        dim3 wblk(32, 8);
        dim3 wgrid(N_PADROWS / 32, KPAD / 32, 3);
        conv_w_all_kernel<<<wgrid, wblk>>>(W0, W1, W2, w0, w1, w2);
    }
    {
        int n = M_DIM * (KPAD0 / 4);
        conv_sent_kernel<<<(n + 255) / 256, 256>>>(sent);
    }

    dim3 ggrid(N_PADROWS / BN, M_DIM / BM);   // (19, 256)
    size_t smem = STAGES * STAGE_BYTES;
    dim3 sgrid(H2 / SJ, B_DIM);               // (25, 64)

    // kk_tail: layer0 real K=300 -> last chunk needs ceil((300-256)/16)=3 groups;
    // layers 1/2 real K=800 -> ceil((800-768)/16)=2 groups.
    qrnn_gemm_kernel<<<ggrid, 256, smem>>>(a0, w0, KPAD0, KPAD0 / BK, 3, b0, g);
    qrnn_scan_fused_kernel<<<sgrid, 256>>>(g, a12, out, 0, 1);

    qrnn_gemm_kernel<<<ggrid, 256, smem>>>(a12, w1, KPAD, KPAD / BK, 2, b1, g);
    qrnn_scan_fused_kernel<<<sgrid, 256>>>(g, a12, out, 1, 1);

    qrnn_gemm_kernel<<<ggrid, 256, smem>>>(a12, w2, KPAD, KPAD / BK, 2, b2, g);
    qrnn_scan_fused_kernel<<<sgrid, 256>>>(g, a12, out, 2, 0);
}